// round 1
// baseline (speedup 1.0000x reference)
#include <cuda_runtime.h>
#include <cstdint>

#define BATCH 16
#define NPT 2048
#define DIM 64
#define NMAT 32   // 2 * BATCH  (0..15 = x/gts, 16..31 = z)

// Scratch (allocation-free rule: __device__ globals)
__device__ float g_D[(size_t)NMAT * NPT * NPT];   // 512 MB: per-(space,batch) distance matrices
__device__ float g_sq[NMAT * NPT];                // squared norms
__device__ int2  g_edges[NMAT * (NPT - 1)];       // MST edges (src, dst)
__device__ float g_partial[NMAT];

// ---------------------------------------------------------------------------
// 1. squared norms
// ---------------------------------------------------------------------------
__global__ void norms_kernel(const float* __restrict__ gts, const float* __restrict__ z) {
    int row = blockIdx.x * blockDim.x + threadIdx.x;
    if (row >= NMAT * NPT) return;
    const float* P = (row < BATCH * NPT) ? gts : z;
    int r = (row < BATCH * NPT) ? row : row - BATCH * NPT;
    const float4* p = (const float4*)(P + (size_t)r * DIM);
    float s = 0.f;
#pragma unroll
    for (int k = 0; k < DIM / 4; k++) {
        float4 v = p[k];
        s += v.x * v.x + v.y * v.y + v.z * v.z + v.w * v.w;
    }
    g_sq[row] = s;
}

// ---------------------------------------------------------------------------
// 2. distance matrices: D = sqrt(max(sq_i + sq_j - 2*dot, 0))
//    64x64 tile per block, 256 threads, 4x4 per thread, K=64 in one stage.
// ---------------------------------------------------------------------------
__global__ void __launch_bounds__(256) dist_kernel(const float* __restrict__ gts,
                                                   const float* __restrict__ z) {
    __shared__ float As[DIM][68];  // [k][i] transposed, padded
    __shared__ float Bs[DIM][68];

    int bm = blockIdx.z;
    const float* P = (bm < BATCH) ? gts + (size_t)bm * NPT * DIM
                                  : z + (size_t)(bm - BATCH) * NPT * DIM;
    int i0 = blockIdx.y * 64;
    int j0 = blockIdx.x * 64;
    int tid = threadIdx.x;

    // load tiles transposed (coalesced global reads, conflict-free smem writes)
    for (int t = tid; t < 64 * DIM; t += 256) {
        int i = t / DIM, k = t % DIM;
        As[k][i] = P[(size_t)(i0 + i) * DIM + k];
        Bs[k][i] = P[(size_t)(j0 + i) * DIM + k];
    }
    __syncthreads();

    int tx = tid & 15;   // j sub-tile
    int ty = tid >> 4;   // i sub-tile
    float c[4][4] = {};
#pragma unroll
    for (int k = 0; k < DIM; k++) {
        float4 a = *(const float4*)&As[k][ty * 4];
        float4 b = *(const float4*)&Bs[k][tx * 4];
        float av[4] = {a.x, a.y, a.z, a.w};
        float bv[4] = {b.x, b.y, b.z, b.w};
#pragma unroll
        for (int r = 0; r < 4; r++)
#pragma unroll
            for (int cc = 0; cc < 4; cc++)
                c[r][cc] += av[r] * bv[cc];
    }

    const float* sqb = g_sq + bm * NPT;
    float sqi[4], sqj[4];
#pragma unroll
    for (int r = 0; r < 4; r++) sqi[r] = sqb[i0 + ty * 4 + r];
#pragma unroll
    for (int cc = 0; cc < 4; cc++) sqj[cc] = sqb[j0 + tx * 4 + cc];

    float* Dm = g_D + (size_t)bm * NPT * NPT;
#pragma unroll
    for (int r = 0; r < 4; r++) {
        int gi = i0 + ty * 4 + r;
        float4 o;
        o.x = sqrtf(fmaxf(sqi[r] + sqj[0] - 2.f * c[r][0], 0.f));
        o.y = sqrtf(fmaxf(sqi[r] + sqj[1] - 2.f * c[r][1], 0.f));
        o.z = sqrtf(fmaxf(sqi[r] + sqj[2] - 2.f * c[r][2], 0.f));
        o.w = sqrtf(fmaxf(sqi[r] + sqj[3] - 2.f * c[r][3], 0.f));
        *(float4*)&Dm[(size_t)gi * NPT + j0 + tx * 4] = o;
    }
}

// ---------------------------------------------------------------------------
// 3. Prim's MST, one block per (space,batch). keys packed (dist_bits<<32)|idx
//    so u64 min == (argmin by dist, first-index tie-break), matching jnp.argmin.
// ---------------------------------------------------------------------------
static __device__ __forceinline__ unsigned long long umin64(unsigned long long a,
                                                            unsigned long long b) {
    return a < b ? a : b;
}

__global__ void __launch_bounds__(1024) prim_kernel() {
    __shared__ unsigned long long key[NPT];  // 16 KB
    __shared__ int src[NPT];                 // 8 KB
    __shared__ unsigned long long wmin[32];
    __shared__ int s_j;

    const unsigned long long VIS = ~0ull;
    int bm = blockIdx.x;
    int tid = threadIdx.x;
    const float* Dm = g_D + (size_t)bm * NPT * NPT;

    // init: node 0 visited, mind = D[0][:]
    for (int idx = tid; idx < NPT; idx += 1024) {
        float d = Dm[idx];
        key[idx] = ((unsigned long long)__float_as_uint(d) << 32) | (unsigned)idx;
        src[idx] = 0;
    }
    if (tid == 0) key[0] = VIS;
    __syncthreads();

    int2* ed = g_edges + bm * (NPT - 1);

    for (int step = 0; step < NPT - 1; step++) {
        // block-wide argmin
        unsigned long long v = umin64(key[tid], key[tid + 1024]);
#pragma unroll
        for (int o = 16; o; o >>= 1)
            v = umin64(v, __shfl_down_sync(0xFFFFFFFFu, v, o));
        if ((tid & 31) == 0) wmin[tid >> 5] = v;
        __syncthreads();
        if (tid < 32) {
            v = wmin[tid];
#pragma unroll
            for (int o = 16; o; o >>= 1)
                v = umin64(v, __shfl_down_sync(0xFFFFFFFFu, v, o));
            if (tid == 0) {
                int j = (int)(unsigned)(v & 0xFFFFFFFFu);
                ed[step] = make_int2(src[j], j);
                key[j] = VIS;
                s_j = j;
            }
        }
        __syncthreads();

        int j = s_j;
        const float* row = Dm + (size_t)j * NPT;
        // relax: issue both loads up-front for MLP, then conditional update
        unsigned long long c0 = key[tid];
        unsigned long long c1 = key[tid + 1024];
        float d0 = row[tid];
        float d1 = row[tid + 1024];
        unsigned long long n0 =
            ((unsigned long long)__float_as_uint(d0) << 32) | (unsigned)tid;
        unsigned long long n1 =
            ((unsigned long long)__float_as_uint(d1) << 32) | (unsigned)(tid + 1024);
        if (c0 != VIS && n0 < c0) { key[tid] = n0; src[tid] = j; }
        if (c1 != VIS && n1 < c1) { key[tid + 1024] = n1; src[tid + 1024] = j; }
        __syncthreads();
    }
}

// ---------------------------------------------------------------------------
// 4. loss: 0.5 * sum over all MST edges (both trees) of (Dx[p]-Dz[p])^2
// ---------------------------------------------------------------------------
__global__ void loss_kernel() {
    int bm = blockIdx.x;          // which tree's edge list
    int b = bm & (BATCH - 1);     // batch index
    const int2* ed = g_edges + bm * (NPT - 1);
    const float* Dx = g_D + (size_t)b * NPT * NPT;
    const float* Dz = g_D + (size_t)(BATCH + b) * NPT * NPT;

    float acc = 0.f;
    for (int e = threadIdx.x; e < NPT - 1; e += 256) {
        int2 p = ed[e];
        float dx = Dx[(size_t)p.x * NPT + p.y];
        float dz = Dz[(size_t)p.x * NPT + p.y];
        float t = dx - dz;
        acc += t * t;
    }
    __shared__ float sm[256];
    sm[threadIdx.x] = acc;
    __syncthreads();
    for (int s = 128; s; s >>= 1) {
        if (threadIdx.x < s) sm[threadIdx.x] += sm[threadIdx.x + s];
        __syncthreads();
    }
    if (threadIdx.x == 0) g_partial[bm] = sm[0];
}

__global__ void final_kernel(float* out) {
    if (threadIdx.x == 0) {
        float s = 0.f;
        for (int i = 0; i < NMAT; i++) s += g_partial[i];
        out[0] = 0.5f * s;
    }
}

// ---------------------------------------------------------------------------
extern "C" void kernel_launch(void* const* d_in, const int* in_sizes, int n_in,
                              void* d_out, int out_size) {
    (void)in_sizes; (void)n_in; (void)out_size;
    const float* gts = (const float*)d_in[0];
    const float* z   = (const float*)d_in[1];

    norms_kernel<<<(NMAT * NPT + 255) / 256, 256>>>(gts, z);

    dim3 g(NPT / 64, NPT / 64, NMAT);
    dist_kernel<<<g, 256>>>(gts, z);

    prim_kernel<<<NMAT, 1024>>>();

    loss_kernel<<<NMAT, 256>>>();
    final_kernel<<<1, 32>>>((float*)d_out);
}